// round 5
// baseline (speedup 1.0000x reference)
#include <cuda_runtime.h>
#include <cstdint>

// Problem constants (fixed by setup_inputs)
#define BATCH 4
#define NPTS  16384
#define NTOT  (BATCH * NPTS)   // 65536
#define NJ    1024
#define CCOND 69
#define HID   256
#define TOPK  5

// Scratch (device globals; no dynamic allocation allowed)
__device__ float4 gPack[BATCH * HID];      // (w1x, w1y, w1z, base_b)  per (b, t)
__device__ float  gW2p[HID * 8];           // W2 row t padded to 8 floats
__device__ float  gRr[BATCH * 9];          // root-orient rotation per batch
__device__ float  gAux[BATCH * 4];         // s, t0, t1, t2
__device__ float  gT[BATCH * NJ * 12];     // top 3x4 rows of final transforms

// ---------------------------------------------------------------------------
// Rodrigues exactly as reference: angle = |a + 1e-8| (eps in norm only),
// axis = a/angle, quat = (cos(h), sin(h)*axis), quat re-normalized in quat2mat.
// ---------------------------------------------------------------------------
__device__ __forceinline__ void rodrigues_mat(float a0, float a1, float a2, float* R) {
    float e0 = a0 + 1e-8f, e1 = a1 + 1e-8f, e2 = a2 + 1e-8f;
    float angle = sqrtf(e0 * e0 + e1 * e1 + e2 * e2);
    float half = 0.5f * angle;
    float s = sinf(half), c = cosf(half);
    float inv = 1.0f / angle;
    float qw = c, qx = s * a0 * inv, qy = s * a1 * inv, qz = s * a2 * inv;
    float qn = rsqrtf(qw * qw + qx * qx + qy * qy + qz * qz);
    qw *= qn; qx *= qn; qy *= qn; qz *= qn;
    float w2 = qw * qw, x2 = qx * qx, y2 = qy * qy, z2 = qz * qz;
    float wx = qw * qx, wy = qw * qy, wz = qw * qz;
    float xy = qx * qy, xz = qx * qz, yz = qy * qz;
    R[0] = w2 + x2 - y2 - z2; R[1] = 2.f * xy - 2.f * wz; R[2] = 2.f * wy + 2.f * xz;
    R[3] = 2.f * wz + 2.f * xy; R[4] = w2 - x2 + y2 - z2; R[5] = 2.f * yz - 2.f * wx;
    R[6] = 2.f * xz - 2.f * wy; R[7] = 2.f * wx + 2.f * yz; R[8] = w2 - x2 - y2 + z2;
}

// ---------------------------------------------------------------------------
// Kernel A: base[b][t] = b1[t] + cond[b] . W1[3:, t].
// R4 post-mortem: single thread per (b,t) serializes 69 loads at MLP~10.
// Now 4 threads per (b,t) (1024-thread block), 17-18 guarded independent
// loads each, smem partial reduce -> ~1 DRAM round trip.
// ---------------------------------------------------------------------------
__global__ __launch_bounds__(4 * HID) void prep_kernel(
        const float* __restrict__ cond,
        const float* __restrict__ W1,
        const float* __restrict__ b1,
        const float* __restrict__ W2,
        const float* __restrict__ root,
        const float* __restrict__ trans,
        const float* __restrict__ scale) {
    __shared__ float part[4][HID];
    int b = blockIdx.x;
    int t = threadIdx.x & (HID - 1);
    int q = threadIdx.x >> 8;            // 0..3
    const float* cb = cond + b * CCOND;

    float s = 0.f;
    #pragma unroll
    for (int i = 0; i < 18; i++) {
        int c = q + 4 * i;
        if (c < CCOND)
            s = fmaf(cb[c], W1[(3 + c) * HID + t], s);
    }
    part[q][t] = s;
    __syncthreads();

    if (q == 0) {
        float acc = b1[t] + ((part[0][t] + part[1][t]) + (part[2][t] + part[3][t]));
        gPack[b * HID + t] = make_float4(W1[t], W1[HID + t], W1[2 * HID + t], acc);
    } else if (q == 1 && b == 0) {
        #pragma unroll
        for (int o = 0; o < 6; o++) gW2p[t * 8 + o] = W2[t * 6 + o];
        gW2p[t * 8 + 6] = 0.f;
        gW2p[t * 8 + 7] = 0.f;
    } else if (q == 2 && t == 0) {
        float R[9];
        rodrigues_mat(root[b * 3], root[b * 3 + 1], root[b * 3 + 2], R);
        #pragma unroll
        for (int i = 0; i < 9; i++) gRr[b * 9 + i] = R[i];
        gAux[b * 4 + 0] = scale[b];
        gAux[b * 4 + 1] = trans[b * 3 + 0];
        gAux[b * 4 + 2] = trans[b * 3 + 1];
        gAux[b * 4 + 3] = trans[b * 3 + 2];
    }
}

// ---------------------------------------------------------------------------
// Kernel B: warp per (b, j). Lane covers 8 hidden units (t = lane + 32*i).
// tf6 = sum_t relu(base + n.w1[t]) * W2[t, :]; then Rodrigues + compose with
// root transform + scale + translation. Stores 3x4 rows to gT.
// ---------------------------------------------------------------------------
__global__ void tmat_kernel(const float* __restrict__ nodes,
                            const float* __restrict__ b2) {
    int gw = (blockIdx.x * blockDim.x + threadIdx.x) >> 5;  // 0..4095
    int lane = threadIdx.x & 31;
    int b = gw >> 10;
    int j = gw & (NJ - 1);

    float n0 = nodes[j * 3], n1 = nodes[j * 3 + 1], n2 = nodes[j * 3 + 2];
    float a0 = 0.f, a1 = 0.f, a2 = 0.f, a3 = 0.f, a4 = 0.f, a5 = 0.f;

    #pragma unroll
    for (int i = 0; i < 8; i++) {
        int t = lane + (i << 5);
        float4 p = gPack[(b << 8) + t];
        float h = fmaf(n0, p.x, fmaf(n1, p.y, fmaf(n2, p.z, p.w)));
        h = fmaxf(h, 0.f);
        const float4* w2v = (const float4*)(gW2p + t * 8);
        float4 lo = w2v[0];
        float4 hi = w2v[1];
        a0 = fmaf(h, lo.x, a0); a1 = fmaf(h, lo.y, a1); a2 = fmaf(h, lo.z, a2);
        a3 = fmaf(h, lo.w, a3); a4 = fmaf(h, hi.x, a4); a5 = fmaf(h, hi.y, a5);
    }
    #pragma unroll
    for (int off = 16; off; off >>= 1) {
        a0 += __shfl_xor_sync(0xffffffffu, a0, off);
        a1 += __shfl_xor_sync(0xffffffffu, a1, off);
        a2 += __shfl_xor_sync(0xffffffffu, a2, off);
        a3 += __shfl_xor_sync(0xffffffffu, a3, off);
        a4 += __shfl_xor_sync(0xffffffffu, a4, off);
        a5 += __shfl_xor_sync(0xffffffffu, a5, off);
    }
    if (lane == 0) {
        float r0 = a0 + b2[0], r1 = a1 + b2[1], r2 = a2 + b2[2];
        float u0 = a3 + b2[3], u1 = a4 + b2[4], u2 = a5 + b2[5];
        float R[9];
        rodrigues_mat(r0, r1, r2, R);
        const float* Rr = gRr + b * 9;
        float s = gAux[b * 4];
        float tr[3] = {gAux[b * 4 + 1], gAux[b * 4 + 2], gAux[b * 4 + 3]};
        float M[12];
        #pragma unroll
        for (int r = 0; r < 3; r++) {
            float c0 = Rr[r * 3], c1 = Rr[r * 3 + 1], c2 = Rr[r * 3 + 2];
            M[r * 4 + 0] = s * (c0 * R[0] + c1 * R[3] + c2 * R[6]);
            M[r * 4 + 1] = s * (c0 * R[1] + c1 * R[4] + c2 * R[7]);
            M[r * 4 + 2] = s * (c0 * R[2] + c1 * R[5] + c2 * R[8]);
            M[r * 4 + 3] = s * (c0 * u0 + c1 * u1 + c2 * u2) + tr[r] * s;
        }
        float4* dst = (float4*)(gT + ((size_t)((b << 10) + j)) * 12);
        dst[0] = make_float4(M[0], M[1], M[2], M[3]);
        dst[1] = make_float4(M[4], M[5], M[6], M[7]);
        dst[2] = make_float4(M[8], M[9], M[10], M[11]);
    }
}

// ---------------------------------------------------------------------------
// Kernel C: per point. Metric t = x.(-2n)+|n|^2 (|x|^2-shifted d^2, ordering-
// invariant). Candidate index packed into the low 10 mantissa bits of t
// (mask+OR: order-preserving; tie-quantum ~2.4e-4 absolute on t, winners get
// exact distances recomputed below). Sorted top-5 insert = 8 FMNMX.
// Grid: 512 blocks x 128 threads.
// ---------------------------------------------------------------------------
__global__ void knn_kernel(const float* __restrict__ x,
                           const float* __restrict__ nodes,
                           float* __restrict__ out) {
    __shared__ float4 sn[NJ];
    int tid = threadIdx.x;
    for (int e = tid; e < NJ; e += 128) {
        float v0 = nodes[e * 3], v1 = nodes[e * 3 + 1], v2 = nodes[e * 3 + 2];
        sn[e] = make_float4(-2.f * v0, -2.f * v1, -2.f * v2,
                            v0 * v0 + v1 * v1 + v2 * v2);
    }
    __syncthreads();

    int p = blockIdx.x * 128 + tid;      // 0..65535
    int b = p >> 14;                     // NPTS = 16384
    float x0 = x[p * 3], x1 = x[p * 3 + 1], x2 = x[p * 3 + 2];
    float xx = x0 * x0 + x1 * x1 + x2 * x2;

    float p0 = 1e30f, p1 = 1e30f, p2 = 1e30f, p3 = 1e30f, p4 = 1e30f;

    #pragma unroll 8
    for (int j = 0; j < NJ; j++) {
        float4 q = sn[j];
        float t = fmaf(x0, q.x, fmaf(x1, q.y, fmaf(x2, q.z, q.w)));
        float f = __uint_as_float((__float_as_uint(t) & 0xFFFFFC00u) | (unsigned)j);
        if (f < p4) {
            // sorted insert (p0<=..<=p4, f<p4 guaranteed): 8 FMNMX
            float n4 = fmaxf(p3, f);
            float n3 = fmaxf(p2, fminf(p3, f));
            float n2 = fmaxf(p1, fminf(p2, f));
            float n1 = fmaxf(p0, fminf(p1, f));
            float n0 = fminf(p0, f);
            p0 = n0; p1 = n1; p2 = n2; p3 = n3; p4 = n4;
        }
    }

    float pk[TOPK] = {p0, p1, p2, p3, p4};

    float wsum = 0.f, o0 = 0.f, o1 = 0.f, o2 = 0.f;
    #pragma unroll
    for (int k = 0; k < TOPK; k++) {
        int jk = (int)(__float_as_uint(pk[k]) & 1023u);
        // recompute exact distance for the winner
        float4 q = sn[jk];
        float t = fmaf(x0, q.x, fmaf(x1, q.y, fmaf(x2, q.z, q.w)));
        float dd = fmaxf(t + xx, 0.f);
        float dist = sqrtf(dd);
        float wk = -logf(fminf(dist, 1.f) - 1e-6f);
        wsum += wk;
        const float4* Tp = (const float4*)(gT + ((size_t)((b << 10) + jk)) * 12);
        float4 r0 = Tp[0], r1 = Tp[1], r2 = Tp[2];
        o0 = fmaf(wk, fmaf(r0.x, x0, fmaf(r0.y, x1, fmaf(r0.z, x2, r0.w))), o0);
        o1 = fmaf(wk, fmaf(r1.x, x0, fmaf(r1.y, x1, fmaf(r1.z, x2, r1.w))), o1);
        o2 = fmaf(wk, fmaf(r2.x, x0, fmaf(r2.y, x1, fmaf(r2.z, x2, r2.w))), o2);
    }
    float inv = 1.f / wsum;
    out[p * 3 + 0] = o0 * inv;
    out[p * 3 + 1] = o1 * inv;
    out[p * 3 + 2] = o2 * inv;
}

// ---------------------------------------------------------------------------
// Inputs (metadata order): x, cond_smpl, nodes, smpl_root_orient, smpl_trans,
// scale, W1, b1, W2, b2.  Output: float32 (B, N, 3).
// ---------------------------------------------------------------------------
extern "C" void kernel_launch(void* const* d_in, const int* in_sizes, int n_in,
                              void* d_out, int out_size) {
    const float* x     = (const float*)d_in[0];
    const float* cond  = (const float*)d_in[1];
    const float* nodes = (const float*)d_in[2];
    const float* root  = (const float*)d_in[3];
    const float* trans = (const float*)d_in[4];
    const float* scale = (const float*)d_in[5];
    const float* W1    = (const float*)d_in[6];
    const float* b1    = (const float*)d_in[7];
    const float* W2    = (const float*)d_in[8];
    const float* b2    = (const float*)d_in[9];
    float* out = (float*)d_out;

    prep_kernel<<<BATCH, 4 * HID>>>(cond, W1, b1, W2, root, trans, scale);
    tmat_kernel<<<(BATCH * NJ * 32) / 256, 256>>>(nodes, b2);
    knn_kernel<<<NTOT / 128, 128>>>(x, nodes, out);
}

// round 6
// speedup vs baseline: 1.0363x; 1.0363x over previous
#include <cuda_runtime.h>
#include <cstdint>

// Problem constants (fixed by setup_inputs)
#define BATCH 4
#define NPTS  16384
#define NTOT  (BATCH * NPTS)   // 65536
#define NJ    1024
#define CCOND 69
#define HID   256
#define TOPK  5

// Scratch (device global; no dynamic allocation allowed)
__device__ float gT[BATCH * NJ * 12];     // top 3x4 rows of final transforms

// ---------------------------------------------------------------------------
// Rodrigues exactly as reference: angle = |a + 1e-8| (eps in norm only),
// axis = a/angle, quat = (cos(h), sin(h)*axis), quat re-normalized in quat2mat.
// ---------------------------------------------------------------------------
__device__ __forceinline__ void rodrigues_mat(float a0, float a1, float a2, float* R) {
    float e0 = a0 + 1e-8f, e1 = a1 + 1e-8f, e2 = a2 + 1e-8f;
    float angle = sqrtf(e0 * e0 + e1 * e1 + e2 * e2);
    float half = 0.5f * angle;
    float s = sinf(half), c = cosf(half);
    float inv = 1.0f / angle;
    float qw = c, qx = s * a0 * inv, qy = s * a1 * inv, qz = s * a2 * inv;
    float qn = rsqrtf(qw * qw + qx * qx + qy * qy + qz * qz);
    qw *= qn; qx *= qn; qy *= qn; qz *= qn;
    float w2 = qw * qw, x2 = qx * qx, y2 = qy * qy, z2 = qz * qz;
    float wx = qw * qx, wy = qw * qy, wz = qw * qz;
    float xy = qx * qy, xz = qx * qz, yz = qy * qz;
    R[0] = w2 + x2 - y2 - z2; R[1] = 2.f * xy - 2.f * wz; R[2] = 2.f * wy + 2.f * xz;
    R[3] = 2.f * wz + 2.f * xy; R[4] = w2 - x2 + y2 - z2; R[5] = 2.f * yz - 2.f * wx;
    R[6] = 2.f * xz - 2.f * wy; R[7] = 2.f * wx + 2.f * yz; R[8] = w2 - x2 - y2 + z2;
}

// ---------------------------------------------------------------------------
// Fused kernel AB: one block = (b, 8 j's), 256 threads.
// Phase 1 (cooperative): thread t computes base[t] = b1[t]+cond[b].W1[3:,t]
// (69-term dot, 4 accumulators; W1 L2-resident, 512 blocks of MLP), packs
// (w1x,w1y,w1z,base) float4 + padded W2 into smem; thread 0 does root
// rotation + aux. Phase 2: warp w -> j = jbase+w, warp-reduced MLP output,
// Rodrigues, compose, scale/trans, store 3x4 rows to gT.
// Grid: BATCH*128 = 512 blocks x 256 threads.
// ---------------------------------------------------------------------------
__global__ __launch_bounds__(256) void tmat_fused_kernel(
        const float* __restrict__ cond,
        const float* __restrict__ W1,
        const float* __restrict__ b1,
        const float* __restrict__ W2,
        const float* __restrict__ nodes,
        const float* __restrict__ root,
        const float* __restrict__ trans,
        const float* __restrict__ scale,
        const float* __restrict__ b2) {
    __shared__ float4 sP[HID];       // (w1x, w1y, w1z, base)
    __shared__ float  sW2[HID * 8];  // W2 row t padded to 8
    __shared__ float  sRr[9];
    __shared__ float  sAux[4];

    int b = blockIdx.x >> 7;               // 0..3
    int jbase = (blockIdx.x & 127) << 3;   // 0,8,...,1016
    int t = threadIdx.x;
    const float* cb = cond + b * CCOND;

    // ---- Phase 1 ----
    float s0 = 0.f, s1 = 0.f, s2 = 0.f, s3 = 0.f;
    #pragma unroll
    for (int c = 0; c < 68; c += 4) {
        s0 = fmaf(cb[c + 0], W1[(3 + c) * HID + t], s0);
        s1 = fmaf(cb[c + 1], W1[(4 + c) * HID + t], s1);
        s2 = fmaf(cb[c + 2], W1[(5 + c) * HID + t], s2);
        s3 = fmaf(cb[c + 3], W1[(6 + c) * HID + t], s3);
    }
    s0 = fmaf(cb[68], W1[71 * HID + t], s0);
    float base = b1[t] + ((s0 + s1) + (s2 + s3));
    sP[t] = make_float4(W1[t], W1[HID + t], W1[2 * HID + t], base);

    #pragma unroll
    for (int o = 0; o < 6; o++) sW2[t * 8 + o] = W2[t * 6 + o];
    sW2[t * 8 + 6] = 0.f;
    sW2[t * 8 + 7] = 0.f;

    if (t == 0) {
        float R[9];
        rodrigues_mat(root[b * 3], root[b * 3 + 1], root[b * 3 + 2], R);
        #pragma unroll
        for (int i = 0; i < 9; i++) sRr[i] = R[i];
        sAux[0] = scale[b];
        sAux[1] = trans[b * 3 + 0];
        sAux[2] = trans[b * 3 + 1];
        sAux[3] = trans[b * 3 + 2];
    }
    __syncthreads();

    // ---- Phase 2 ----
    int w = t >> 5;
    int lane = t & 31;
    int j = jbase + w;

    float n0 = nodes[j * 3], n1 = nodes[j * 3 + 1], n2 = nodes[j * 3 + 2];
    float a0 = 0.f, a1 = 0.f, a2 = 0.f, a3 = 0.f, a4 = 0.f, a5 = 0.f;

    #pragma unroll
    for (int i = 0; i < 8; i++) {
        int tt = lane + (i << 5);
        float4 p = sP[tt];
        float h = fmaf(n0, p.x, fmaf(n1, p.y, fmaf(n2, p.z, p.w)));
        h = fmaxf(h, 0.f);
        const float4* w2v = (const float4*)(sW2 + tt * 8);
        float4 lo = w2v[0];
        float4 hi = w2v[1];
        a0 = fmaf(h, lo.x, a0); a1 = fmaf(h, lo.y, a1); a2 = fmaf(h, lo.z, a2);
        a3 = fmaf(h, lo.w, a3); a4 = fmaf(h, hi.x, a4); a5 = fmaf(h, hi.y, a5);
    }
    #pragma unroll
    for (int off = 16; off; off >>= 1) {
        a0 += __shfl_xor_sync(0xffffffffu, a0, off);
        a1 += __shfl_xor_sync(0xffffffffu, a1, off);
        a2 += __shfl_xor_sync(0xffffffffu, a2, off);
        a3 += __shfl_xor_sync(0xffffffffu, a3, off);
        a4 += __shfl_xor_sync(0xffffffffu, a4, off);
        a5 += __shfl_xor_sync(0xffffffffu, a5, off);
    }
    if (lane == 0) {
        float r0 = a0 + b2[0], r1 = a1 + b2[1], r2 = a2 + b2[2];
        float u0 = a3 + b2[3], u1 = a4 + b2[4], u2 = a5 + b2[5];
        float R[9];
        rodrigues_mat(r0, r1, r2, R);
        float s = sAux[0];
        float M[12];
        #pragma unroll
        for (int r = 0; r < 3; r++) {
            float c0 = sRr[r * 3], c1 = sRr[r * 3 + 1], c2 = sRr[r * 3 + 2];
            M[r * 4 + 0] = s * (c0 * R[0] + c1 * R[3] + c2 * R[6]);
            M[r * 4 + 1] = s * (c0 * R[1] + c1 * R[4] + c2 * R[7]);
            M[r * 4 + 2] = s * (c0 * R[2] + c1 * R[5] + c2 * R[8]);
            M[r * 4 + 3] = s * (c0 * u0 + c1 * u1 + c2 * u2) + sAux[1 + r] * s;
        }
        float4* dst = (float4*)(gT + ((size_t)((b << 10) + j)) * 12);
        dst[0] = make_float4(M[0], M[1], M[2], M[3]);
        dst[1] = make_float4(M[4], M[5], M[6], M[7]);
        dst[2] = make_float4(M[8], M[9], M[10], M[11]);
    }
}

// ---------------------------------------------------------------------------
// Kernel C: per point. Metric t = x.(-2n)+|n|^2 (|x|^2-shifted d^2, ordering-
// invariant). Candidate index packed into low 10 mantissa bits (order-
// preserving mask+OR; winners get exact distances recomputed). Sorted top-5
// insert = 8 FMNMX. Grid: 512 blocks x 128 threads.
// ---------------------------------------------------------------------------
__global__ void knn_kernel(const float* __restrict__ x,
                           const float* __restrict__ nodes,
                           float* __restrict__ out) {
    __shared__ float4 sn[NJ];
    int tid = threadIdx.x;
    for (int e = tid; e < NJ; e += 128) {
        float v0 = nodes[e * 3], v1 = nodes[e * 3 + 1], v2 = nodes[e * 3 + 2];
        sn[e] = make_float4(-2.f * v0, -2.f * v1, -2.f * v2,
                            v0 * v0 + v1 * v1 + v2 * v2);
    }
    __syncthreads();

    int p = blockIdx.x * 128 + tid;      // 0..65535
    int b = p >> 14;                     // NPTS = 16384
    float x0 = x[p * 3], x1 = x[p * 3 + 1], x2 = x[p * 3 + 2];
    float xx = x0 * x0 + x1 * x1 + x2 * x2;

    float p0 = 1e30f, p1 = 1e30f, p2 = 1e30f, p3 = 1e30f, p4 = 1e30f;

    #pragma unroll 16
    for (int j = 0; j < NJ; j++) {
        float4 q = sn[j];
        float t = fmaf(x0, q.x, fmaf(x1, q.y, fmaf(x2, q.z, q.w)));
        float f = __uint_as_float((__float_as_uint(t) & 0xFFFFFC00u) | (unsigned)j);
        if (f < p4) {
            float n4 = fmaxf(p3, f);
            float n3 = fmaxf(p2, fminf(p3, f));
            float n2 = fmaxf(p1, fminf(p2, f));
            float n1 = fmaxf(p0, fminf(p1, f));
            float n0 = fminf(p0, f);
            p0 = n0; p1 = n1; p2 = n2; p3 = n3; p4 = n4;
        }
    }

    float pk[TOPK] = {p0, p1, p2, p3, p4};

    float wsum = 0.f, o0 = 0.f, o1 = 0.f, o2 = 0.f;
    #pragma unroll
    for (int k = 0; k < TOPK; k++) {
        int jk = (int)(__float_as_uint(pk[k]) & 1023u);
        float4 q = sn[jk];
        float t = fmaf(x0, q.x, fmaf(x1, q.y, fmaf(x2, q.z, q.w)));
        float dd = fmaxf(t + xx, 0.f);
        float dist = sqrtf(dd);
        float wk = -logf(fminf(dist, 1.f) - 1e-6f);
        wsum += wk;
        const float4* Tp = (const float4*)(gT + ((size_t)((b << 10) + jk)) * 12);
        float4 r0 = Tp[0], r1 = Tp[1], r2 = Tp[2];
        o0 = fmaf(wk, fmaf(r0.x, x0, fmaf(r0.y, x1, fmaf(r0.z, x2, r0.w))), o0);
        o1 = fmaf(wk, fmaf(r1.x, x0, fmaf(r1.y, x1, fmaf(r1.z, x2, r1.w))), o1);
        o2 = fmaf(wk, fmaf(r2.x, x0, fmaf(r2.y, x1, fmaf(r2.z, x2, r2.w))), o2);
    }
    float inv = 1.f / wsum;
    out[p * 3 + 0] = o0 * inv;
    out[p * 3 + 1] = o1 * inv;
    out[p * 3 + 2] = o2 * inv;
}

// ---------------------------------------------------------------------------
// Inputs (metadata order): x, cond_smpl, nodes, smpl_root_orient, smpl_trans,
// scale, W1, b1, W2, b2.  Output: float32 (B, N, 3).
// ---------------------------------------------------------------------------
extern "C" void kernel_launch(void* const* d_in, const int* in_sizes, int n_in,
                              void* d_out, int out_size) {
    const float* x     = (const float*)d_in[0];
    const float* cond  = (const float*)d_in[1];
    const float* nodes = (const float*)d_in[2];
    const float* root  = (const float*)d_in[3];
    const float* trans = (const float*)d_in[4];
    const float* scale = (const float*)d_in[5];
    const float* W1    = (const float*)d_in[6];
    const float* b1    = (const float*)d_in[7];
    const float* W2    = (const float*)d_in[8];
    const float* b2    = (const float*)d_in[9];
    float* out = (float*)d_out;

    tmat_fused_kernel<<<BATCH * 128, 256>>>(cond, W1, b1, W2, nodes,
                                            root, trans, scale, b2);
    knn_kernel<<<NTOT / 128, 128>>>(x, nodes, out);
}

// round 7
// speedup vs baseline: 1.1158x; 1.0767x over previous
#include <cuda_runtime.h>
#include <cstdint>

// Problem constants (fixed by setup_inputs)
#define BATCH 4
#define NPTS  16384
#define NTOT  (BATCH * NPTS)   // 65536
#define NJ    1024
#define CCOND 69
#define HID   256
#define TOPK  5

// Scratch (device global; no dynamic allocation allowed)
__device__ float gT[BATCH * NJ * 12];     // top 3x4 rows of final transforms

// ---------------------------------------------------------------------------
// Rodrigues exactly as reference.
// ---------------------------------------------------------------------------
__device__ __forceinline__ void rodrigues_mat(float a0, float a1, float a2, float* R) {
    float e0 = a0 + 1e-8f, e1 = a1 + 1e-8f, e2 = a2 + 1e-8f;
    float angle = sqrtf(e0 * e0 + e1 * e1 + e2 * e2);
    float half = 0.5f * angle;
    float s = sinf(half), c = cosf(half);
    float inv = 1.0f / angle;
    float qw = c, qx = s * a0 * inv, qy = s * a1 * inv, qz = s * a2 * inv;
    float qn = rsqrtf(qw * qw + qx * qx + qy * qy + qz * qz);
    qw *= qn; qx *= qn; qy *= qn; qz *= qn;
    float w2 = qw * qw, x2 = qx * qx, y2 = qy * qy, z2 = qz * qz;
    float wx = qw * qx, wy = qw * qy, wz = qw * qz;
    float xy = qx * qy, xz = qx * qz, yz = qy * qz;
    R[0] = w2 + x2 - y2 - z2; R[1] = 2.f * xy - 2.f * wz; R[2] = 2.f * wy + 2.f * xz;
    R[3] = 2.f * wz + 2.f * xy; R[4] = w2 - x2 + y2 - z2; R[5] = 2.f * yz - 2.f * wx;
    R[6] = 2.f * xz - 2.f * wy; R[7] = 2.f * wx + 2.f * yz; R[8] = w2 - x2 - y2 + z2;
}

// ---------------------------------------------------------------------------
// Fused kernel AB (unchanged from R6): one block = (b, 8 j's), 256 threads.
// ---------------------------------------------------------------------------
__global__ __launch_bounds__(256) void tmat_fused_kernel(
        const float* __restrict__ cond,
        const float* __restrict__ W1,
        const float* __restrict__ b1,
        const float* __restrict__ W2,
        const float* __restrict__ nodes,
        const float* __restrict__ root,
        const float* __restrict__ trans,
        const float* __restrict__ scale,
        const float* __restrict__ b2) {
    __shared__ float4 sP[HID];
    __shared__ float  sW2[HID * 8];
    __shared__ float  sRr[9];
    __shared__ float  sAux[4];

    int b = blockIdx.x >> 7;
    int jbase = (blockIdx.x & 127) << 3;
    int t = threadIdx.x;
    const float* cb = cond + b * CCOND;

    float s0 = 0.f, s1 = 0.f, s2 = 0.f, s3 = 0.f;
    #pragma unroll
    for (int c = 0; c < 68; c += 4) {
        s0 = fmaf(cb[c + 0], W1[(3 + c) * HID + t], s0);
        s1 = fmaf(cb[c + 1], W1[(4 + c) * HID + t], s1);
        s2 = fmaf(cb[c + 2], W1[(5 + c) * HID + t], s2);
        s3 = fmaf(cb[c + 3], W1[(6 + c) * HID + t], s3);
    }
    s0 = fmaf(cb[68], W1[71 * HID + t], s0);
    float base = b1[t] + ((s0 + s1) + (s2 + s3));
    sP[t] = make_float4(W1[t], W1[HID + t], W1[2 * HID + t], base);

    #pragma unroll
    for (int o = 0; o < 6; o++) sW2[t * 8 + o] = W2[t * 6 + o];
    sW2[t * 8 + 6] = 0.f;
    sW2[t * 8 + 7] = 0.f;

    if (t == 0) {
        float R[9];
        rodrigues_mat(root[b * 3], root[b * 3 + 1], root[b * 3 + 2], R);
        #pragma unroll
        for (int i = 0; i < 9; i++) sRr[i] = R[i];
        sAux[0] = scale[b];
        sAux[1] = trans[b * 3 + 0];
        sAux[2] = trans[b * 3 + 1];
        sAux[3] = trans[b * 3 + 2];
    }
    __syncthreads();

    int w = t >> 5;
    int lane = t & 31;
    int j = jbase + w;

    float n0 = nodes[j * 3], n1 = nodes[j * 3 + 1], n2 = nodes[j * 3 + 2];
    float a0 = 0.f, a1 = 0.f, a2 = 0.f, a3 = 0.f, a4 = 0.f, a5 = 0.f;

    #pragma unroll
    for (int i = 0; i < 8; i++) {
        int tt = lane + (i << 5);
        float4 p = sP[tt];
        float h = fmaf(n0, p.x, fmaf(n1, p.y, fmaf(n2, p.z, p.w)));
        h = fmaxf(h, 0.f);
        const float4* w2v = (const float4*)(sW2 + tt * 8);
        float4 lo = w2v[0];
        float4 hi = w2v[1];
        a0 = fmaf(h, lo.x, a0); a1 = fmaf(h, lo.y, a1); a2 = fmaf(h, lo.z, a2);
        a3 = fmaf(h, lo.w, a3); a4 = fmaf(h, hi.x, a4); a5 = fmaf(h, hi.y, a5);
    }
    #pragma unroll
    for (int off = 16; off; off >>= 1) {
        a0 += __shfl_xor_sync(0xffffffffu, a0, off);
        a1 += __shfl_xor_sync(0xffffffffu, a1, off);
        a2 += __shfl_xor_sync(0xffffffffu, a2, off);
        a3 += __shfl_xor_sync(0xffffffffu, a3, off);
        a4 += __shfl_xor_sync(0xffffffffu, a4, off);
        a5 += __shfl_xor_sync(0xffffffffu, a5, off);
    }
    if (lane == 0) {
        float r0 = a0 + b2[0], r1 = a1 + b2[1], r2 = a2 + b2[2];
        float u0 = a3 + b2[3], u1 = a4 + b2[4], u2 = a5 + b2[5];
        float R[9];
        rodrigues_mat(r0, r1, r2, R);
        float s = sAux[0];
        float M[12];
        #pragma unroll
        for (int r = 0; r < 3; r++) {
            float c0 = sRr[r * 3], c1 = sRr[r * 3 + 1], c2 = sRr[r * 3 + 2];
            M[r * 4 + 0] = s * (c0 * R[0] + c1 * R[3] + c2 * R[6]);
            M[r * 4 + 1] = s * (c0 * R[1] + c1 * R[4] + c2 * R[7]);
            M[r * 4 + 2] = s * (c0 * R[2] + c1 * R[5] + c2 * R[8]);
            M[r * 4 + 3] = s * (c0 * u0 + c1 * u1 + c2 * u2) + sAux[1 + r] * s;
        }
        float4* dst = (float4*)(gT + ((size_t)((b << 10) + j)) * 12);
        dst[0] = make_float4(M[0], M[1], M[2], M[3]);
        dst[1] = make_float4(M[4], M[5], M[6], M[7]);
        dst[2] = make_float4(M[8], M[9], M[10], M[11]);
    }
}

// compare-and-swap on packed metrics
#define CAS(a, b) { float _lo = fminf(a, b), _hi = fmaxf(a, b); a = _lo; b = _hi; }

// ---------------------------------------------------------------------------
// Kernel C: 128 threads = 64 points x 2 candidate-halves (occupancy 2x).
// Chunk-of-4 selection: sort4 (10 FMNMX) + narrowing merge into sorted top-5
// (9+7+5+3 = 24 FMNMX) -> 8.5 FMNMX/candidate flat, no data-dependent branch.
// Index packed into low 10 mantissa bits (order-preserving; exact distances
// recomputed for winners). Halves merged via smem (26 FMNMX, once per point).
// Grid: 1024 blocks x 128 threads.
// ---------------------------------------------------------------------------
__global__ __launch_bounds__(128) void knn_kernel(const float* __restrict__ x,
                                                  const float* __restrict__ nodes,
                                                  float* __restrict__ out) {
    __shared__ float4 sn[NJ];
    __shared__ float  mbuf[64][10];
    int tid = threadIdx.x;
    for (int e = tid; e < NJ; e += 128) {
        float v0 = nodes[e * 3], v1 = nodes[e * 3 + 1], v2 = nodes[e * 3 + 2];
        sn[e] = make_float4(-2.f * v0, -2.f * v1, -2.f * v2,
                            v0 * v0 + v1 * v1 + v2 * v2);
    }
    __syncthreads();

    int lpt  = tid & 63;
    int half = tid >> 6;
    int p = blockIdx.x * 64 + lpt;       // 0..65535
    float x0 = x[p * 3], x1 = x[p * 3 + 1], x2 = x[p * 3 + 2];

    float p0 = 1e30f, p1 = 1e30f, p2 = 1e30f, p3 = 1e30f, p4 = 1e30f;
    int jbase = half << 9;               // 0 or 512

    #pragma unroll 2
    for (int c = 0; c < 128; c++) {
        int j = jbase + (c << 2);
        float4 q0 = sn[j], q1 = sn[j + 1], q2 = sn[j + 2], q3 = sn[j + 3];
        float t0 = fmaf(x0, q0.x, fmaf(x1, q0.y, fmaf(x2, q0.z, q0.w)));
        float t1 = fmaf(x0, q1.x, fmaf(x1, q1.y, fmaf(x2, q1.z, q1.w)));
        float t2 = fmaf(x0, q2.x, fmaf(x1, q2.y, fmaf(x2, q2.z, q2.w)));
        float t3 = fmaf(x0, q3.x, fmaf(x1, q3.y, fmaf(x2, q3.z, q3.w)));
        float f0 = __uint_as_float((__float_as_uint(t0) & 0xFFFFFC00u) | (unsigned)(j));
        float f1 = __uint_as_float((__float_as_uint(t1) & 0xFFFFFC00u) | (unsigned)(j + 1));
        float f2 = __uint_as_float((__float_as_uint(t2) & 0xFFFFFC00u) | (unsigned)(j + 2));
        float f3 = __uint_as_float((__float_as_uint(t3) & 0xFFFFFC00u) | (unsigned)(j + 3));
        // sort4: f0<=f1<=f2<=f3
        CAS(f0, f1); CAS(f2, f3); CAS(f0, f2); CAS(f1, f3); CAS(f1, f2);
        // insert f0 (full, 9)
        float n0 = fminf(p0, f0);
        float n1 = fmaxf(p0, fminf(p1, f0));
        float n2 = fmaxf(p1, fminf(p2, f0));
        float n3 = fmaxf(p2, fminf(p3, f0));
        float n4 = fmaxf(p3, fminf(p4, f0));
        // insert f1 (pos>=1, 7)
        float m1 = fminf(n1, f1);
        float m2 = fmaxf(n1, fminf(n2, f1));
        float m3 = fmaxf(n2, fminf(n3, f1));
        float m4 = fmaxf(n3, fminf(n4, f1));
        // insert f2 (pos>=2, 5)
        float k2 = fminf(m2, f2);
        float k3 = fmaxf(m2, fminf(m3, f2));
        float k4 = fmaxf(m3, fminf(m4, f2));
        // insert f3 (pos>=3, 3)
        p0 = n0; p1 = m1; p2 = k2;
        p3 = fminf(k3, f3);
        p4 = fmaxf(k3, fminf(k4, f3));
    }

    mbuf[lpt][half * 5 + 0] = p0;
    mbuf[lpt][half * 5 + 1] = p1;
    mbuf[lpt][half * 5 + 2] = p2;
    mbuf[lpt][half * 5 + 3] = p3;
    mbuf[lpt][half * 5 + 4] = p4;
    __syncthreads();

    if (half == 0) {
        // merge other half's sorted-5 into mine (narrowing: 9+7+5+3+2)
        float b0 = mbuf[lpt][5], b1v = mbuf[lpt][6], b2v = mbuf[lpt][7],
              b3v = mbuf[lpt][8], b4v = mbuf[lpt][9];
        float n0 = fminf(p0, b0);
        float n1 = fmaxf(p0, fminf(p1, b0));
        float n2 = fmaxf(p1, fminf(p2, b0));
        float n3 = fmaxf(p2, fminf(p3, b0));
        float n4 = fmaxf(p3, fminf(p4, b0));
        float m1 = fminf(n1, b1v);
        float m2 = fmaxf(n1, fminf(n2, b1v));
        float m3 = fmaxf(n2, fminf(n3, b1v));
        float m4 = fmaxf(n3, fminf(n4, b1v));
        float k2 = fminf(m2, b2v);
        float k3 = fmaxf(m2, fminf(m3, b2v));
        float k4 = fmaxf(m3, fminf(m4, b2v));
        float l3 = fminf(k3, b3v);
        float l4 = fmaxf(k3, fminf(k4, b3v));
        float o4 = fmaxf(l3, fminf(l4, b4v));
        float pk[TOPK] = {n0, m1, k2, l3, o4};

        int b = p >> 14;
        float xx = x0 * x0 + x1 * x1 + x2 * x2;
        float wsum = 0.f, o0 = 0.f, o1 = 0.f, o2 = 0.f;
        #pragma unroll
        for (int k = 0; k < TOPK; k++) {
            int jk = (int)(__float_as_uint(pk[k]) & 1023u);
            float4 q = sn[jk];
            float t = fmaf(x0, q.x, fmaf(x1, q.y, fmaf(x2, q.z, q.w)));
            float dd = fmaxf(t + xx, 0.f);
            float dist = sqrtf(dd);
            float wk = -logf(fminf(dist, 1.f) - 1e-6f);
            wsum += wk;
            const float4* Tp = (const float4*)(gT + ((size_t)((b << 10) + jk)) * 12);
            float4 r0 = Tp[0], r1 = Tp[1], r2 = Tp[2];
            o0 = fmaf(wk, fmaf(r0.x, x0, fmaf(r0.y, x1, fmaf(r0.z, x2, r0.w))), o0);
            o1 = fmaf(wk, fmaf(r1.x, x0, fmaf(r1.y, x1, fmaf(r1.z, x2, r1.w))), o1);
            o2 = fmaf(wk, fmaf(r2.x, x0, fmaf(r2.y, x1, fmaf(r2.z, x2, r2.w))), o2);
        }
        float inv = 1.f / wsum;
        out[p * 3 + 0] = o0 * inv;
        out[p * 3 + 1] = o1 * inv;
        out[p * 3 + 2] = o2 * inv;
    }
}

// ---------------------------------------------------------------------------
// Inputs (metadata order): x, cond_smpl, nodes, smpl_root_orient, smpl_trans,
// scale, W1, b1, W2, b2.  Output: float32 (B, N, 3).
// ---------------------------------------------------------------------------
extern "C" void kernel_launch(void* const* d_in, const int* in_sizes, int n_in,
                              void* d_out, int out_size) {
    const float* x     = (const float*)d_in[0];
    const float* cond  = (const float*)d_in[1];
    const float* nodes = (const float*)d_in[2];
    const float* root  = (const float*)d_in[3];
    const float* trans = (const float*)d_in[4];
    const float* scale = (const float*)d_in[5];
    const float* W1    = (const float*)d_in[6];
    const float* b1    = (const float*)d_in[7];
    const float* W2    = (const float*)d_in[8];
    const float* b2    = (const float*)d_in[9];
    float* out = (float*)d_out;

    tmat_fused_kernel<<<BATCH * 128, 256>>>(cond, W1, b1, W2, nodes,
                                            root, trans, scale, b2);
    knn_kernel<<<NTOT / 64, 128>>>(x, nodes, out);
}

// round 8
// speedup vs baseline: 1.1511x; 1.0316x over previous
#include <cuda_runtime.h>
#include <cstdint>

// Problem constants (fixed by setup_inputs)
#define BATCH 4
#define NPTS  16384
#define NTOT  (BATCH * NPTS)   // 65536
#define NJ    1024
#define CCOND 69
#define HID   256
#define TOPK  5

// Scratch (device global; no dynamic allocation allowed)
__device__ float gT[BATCH * NJ * 12];     // top 3x4 rows of final transforms

// ---------------------------------------------------------------------------
// Rodrigues exactly as reference.
// ---------------------------------------------------------------------------
__device__ __forceinline__ void rodrigues_mat(float a0, float a1, float a2, float* R) {
    float e0 = a0 + 1e-8f, e1 = a1 + 1e-8f, e2 = a2 + 1e-8f;
    float angle = sqrtf(e0 * e0 + e1 * e1 + e2 * e2);
    float half = 0.5f * angle;
    float s = sinf(half), c = cosf(half);
    float inv = 1.0f / angle;
    float qw = c, qx = s * a0 * inv, qy = s * a1 * inv, qz = s * a2 * inv;
    float qn = rsqrtf(qw * qw + qx * qx + qy * qy + qz * qz);
    qw *= qn; qx *= qn; qy *= qn; qz *= qn;
    float w2 = qw * qw, x2 = qx * qx, y2 = qy * qy, z2 = qz * qz;
    float wx = qw * qx, wy = qw * qy, wz = qw * qz;
    float xy = qx * qy, xz = qx * qz, yz = qy * qz;
    R[0] = w2 + x2 - y2 - z2; R[1] = 2.f * xy - 2.f * wz; R[2] = 2.f * wy + 2.f * xz;
    R[3] = 2.f * wz + 2.f * xy; R[4] = w2 - x2 + y2 - z2; R[5] = 2.f * yz - 2.f * wx;
    R[6] = 2.f * xz - 2.f * wy; R[7] = 2.f * wx + 2.f * yz; R[8] = w2 - x2 - y2 + z2;
}

// ---------------------------------------------------------------------------
// Fused kernel AB (unchanged): one block = (b, 8 j's), 256 threads.
// ---------------------------------------------------------------------------
__global__ __launch_bounds__(256) void tmat_fused_kernel(
        const float* __restrict__ cond,
        const float* __restrict__ W1,
        const float* __restrict__ b1,
        const float* __restrict__ W2,
        const float* __restrict__ nodes,
        const float* __restrict__ root,
        const float* __restrict__ trans,
        const float* __restrict__ scale,
        const float* __restrict__ b2) {
    __shared__ float4 sP[HID];
    __shared__ float  sW2[HID * 8];
    __shared__ float  sRr[9];
    __shared__ float  sAux[4];

    int b = blockIdx.x >> 7;
    int jbase = (blockIdx.x & 127) << 3;
    int t = threadIdx.x;
    const float* cb = cond + b * CCOND;

    float s0 = 0.f, s1 = 0.f, s2 = 0.f, s3 = 0.f;
    #pragma unroll
    for (int c = 0; c < 68; c += 4) {
        s0 = fmaf(cb[c + 0], W1[(3 + c) * HID + t], s0);
        s1 = fmaf(cb[c + 1], W1[(4 + c) * HID + t], s1);
        s2 = fmaf(cb[c + 2], W1[(5 + c) * HID + t], s2);
        s3 = fmaf(cb[c + 3], W1[(6 + c) * HID + t], s3);
    }
    s0 = fmaf(cb[68], W1[71 * HID + t], s0);
    float base = b1[t] + ((s0 + s1) + (s2 + s3));
    sP[t] = make_float4(W1[t], W1[HID + t], W1[2 * HID + t], base);

    #pragma unroll
    for (int o = 0; o < 6; o++) sW2[t * 8 + o] = W2[t * 6 + o];
    sW2[t * 8 + 6] = 0.f;
    sW2[t * 8 + 7] = 0.f;

    if (t == 0) {
        float R[9];
        rodrigues_mat(root[b * 3], root[b * 3 + 1], root[b * 3 + 2], R);
        #pragma unroll
        for (int i = 0; i < 9; i++) sRr[i] = R[i];
        sAux[0] = scale[b];
        sAux[1] = trans[b * 3 + 0];
        sAux[2] = trans[b * 3 + 1];
        sAux[3] = trans[b * 3 + 2];
    }
    __syncthreads();

    int w = t >> 5;
    int lane = t & 31;
    int j = jbase + w;

    float n0 = nodes[j * 3], n1 = nodes[j * 3 + 1], n2 = nodes[j * 3 + 2];
    float a0 = 0.f, a1 = 0.f, a2 = 0.f, a3 = 0.f, a4 = 0.f, a5 = 0.f;

    #pragma unroll
    for (int i = 0; i < 8; i++) {
        int tt = lane + (i << 5);
        float4 p = sP[tt];
        float h = fmaf(n0, p.x, fmaf(n1, p.y, fmaf(n2, p.z, p.w)));
        h = fmaxf(h, 0.f);
        const float4* w2v = (const float4*)(sW2 + tt * 8);
        float4 lo = w2v[0];
        float4 hi = w2v[1];
        a0 = fmaf(h, lo.x, a0); a1 = fmaf(h, lo.y, a1); a2 = fmaf(h, lo.z, a2);
        a3 = fmaf(h, lo.w, a3); a4 = fmaf(h, hi.x, a4); a5 = fmaf(h, hi.y, a5);
    }
    #pragma unroll
    for (int off = 16; off; off >>= 1) {
        a0 += __shfl_xor_sync(0xffffffffu, a0, off);
        a1 += __shfl_xor_sync(0xffffffffu, a1, off);
        a2 += __shfl_xor_sync(0xffffffffu, a2, off);
        a3 += __shfl_xor_sync(0xffffffffu, a3, off);
        a4 += __shfl_xor_sync(0xffffffffu, a4, off);
        a5 += __shfl_xor_sync(0xffffffffu, a5, off);
    }
    if (lane == 0) {
        float r0 = a0 + b2[0], r1 = a1 + b2[1], r2 = a2 + b2[2];
        float u0 = a3 + b2[3], u1 = a4 + b2[4], u2 = a5 + b2[5];
        float R[9];
        rodrigues_mat(r0, r1, r2, R);
        float s = sAux[0];
        float M[12];
        #pragma unroll
        for (int r = 0; r < 3; r++) {
            float c0 = sRr[r * 3], c1 = sRr[r * 3 + 1], c2 = sRr[r * 3 + 2];
            M[r * 4 + 0] = s * (c0 * R[0] + c1 * R[3] + c2 * R[6]);
            M[r * 4 + 1] = s * (c0 * R[1] + c1 * R[4] + c2 * R[7]);
            M[r * 4 + 2] = s * (c0 * R[2] + c1 * R[5] + c2 * R[8]);
            M[r * 4 + 3] = s * (c0 * u0 + c1 * u1 + c2 * u2) + sAux[1 + r] * s;
        }
        float4* dst = (float4*)(gT + ((size_t)((b << 10) + j)) * 12);
        dst[0] = make_float4(M[0], M[1], M[2], M[3]);
        dst[1] = make_float4(M[4], M[5], M[6], M[7]);
        dst[2] = make_float4(M[8], M[9], M[10], M[11]);
    }
}

// compare-and-swap on packed metrics
#define CAS(a, b) { float _lo = fminf(a, b), _hi = fmaxf(a, b); a = _lo; b = _hi; }

// Narrowing merge of a sorted-5 list (b0<=..<=b4) into sorted top-5 p0..p4.
__device__ __forceinline__ void merge5(float& p0, float& p1, float& p2,
                                       float& p3, float& p4,
                                       float b0, float b1, float b2,
                                       float b3, float b4) {
    float n0 = fminf(p0, b0);
    float n1 = fmaxf(p0, fminf(p1, b0));
    float n2 = fmaxf(p1, fminf(p2, b0));
    float n3 = fmaxf(p2, fminf(p3, b0));
    float n4 = fmaxf(p3, fminf(p4, b0));
    float m1 = fminf(n1, b1);
    float m2 = fmaxf(n1, fminf(n2, b1));
    float m3 = fmaxf(n2, fminf(n3, b1));
    float m4 = fmaxf(n3, fminf(n4, b1));
    float k2 = fminf(m2, b2);
    float k3 = fmaxf(m2, fminf(m3, b2));
    float k4 = fmaxf(m3, fminf(m4, b2));
    float l3 = fminf(k3, b3);
    float l4 = fmaxf(k3, fminf(k4, b3));
    p0 = n0; p1 = m1; p2 = k2; p3 = l3;
    p4 = fmaxf(l3, fminf(l4, b4));
}

// ---------------------------------------------------------------------------
// Kernel C: 256 threads = 64 points x 4 candidate-segments (256 js each).
// Chunk-of-4 selection (sort4 + narrowing merge, 8.5 FMNMX/cand flat), index
// packed into low 10 mantissa bits (order-preserving; exact distances
// recomputed for winners). Segment lists merged via smem (3x merge5/point).
// Grid: 1024 blocks x 256 threads; __launch_bounds__(256,6) for 48 warps/SM.
// ---------------------------------------------------------------------------
__global__ __launch_bounds__(256, 6) void knn_kernel(
        const float* __restrict__ x,
        const float* __restrict__ nodes,
        float* __restrict__ out) {
    __shared__ float4 sn[NJ];
    __shared__ float  mbuf[64][17];   // 3 foreign segs * 5, odd stride
    int tid = threadIdx.x;
    for (int e = tid; e < NJ; e += 256) {
        float v0 = nodes[e * 3], v1 = nodes[e * 3 + 1], v2 = nodes[e * 3 + 2];
        sn[e] = make_float4(-2.f * v0, -2.f * v1, -2.f * v2,
                            v0 * v0 + v1 * v1 + v2 * v2);
    }
    __syncthreads();

    int lpt = tid & 63;
    int seg = tid >> 6;                  // 0..3
    int p = blockIdx.x * 64 + lpt;       // 0..65535
    float x0 = x[p * 3], x1 = x[p * 3 + 1], x2 = x[p * 3 + 2];

    float p0 = 1e30f, p1 = 1e30f, p2 = 1e30f, p3 = 1e30f, p4 = 1e30f;
    int jbase = seg << 8;                // 256 candidates per segment

    #pragma unroll 2
    for (int c = 0; c < 64; c++) {
        int j = jbase + (c << 2);
        float4 q0 = sn[j], q1 = sn[j + 1], q2 = sn[j + 2], q3 = sn[j + 3];
        float t0 = fmaf(x0, q0.x, fmaf(x1, q0.y, fmaf(x2, q0.z, q0.w)));
        float t1 = fmaf(x0, q1.x, fmaf(x1, q1.y, fmaf(x2, q1.z, q1.w)));
        float t2 = fmaf(x0, q2.x, fmaf(x1, q2.y, fmaf(x2, q2.z, q2.w)));
        float t3 = fmaf(x0, q3.x, fmaf(x1, q3.y, fmaf(x2, q3.z, q3.w)));
        float f0 = __uint_as_float((__float_as_uint(t0) & 0xFFFFFC00u) | (unsigned)(j));
        float f1 = __uint_as_float((__float_as_uint(t1) & 0xFFFFFC00u) | (unsigned)(j + 1));
        float f2 = __uint_as_float((__float_as_uint(t2) & 0xFFFFFC00u) | (unsigned)(j + 2));
        float f3 = __uint_as_float((__float_as_uint(t3) & 0xFFFFFC00u) | (unsigned)(j + 3));
        // sort4: f0<=f1<=f2<=f3
        CAS(f0, f1); CAS(f2, f3); CAS(f0, f2); CAS(f1, f3); CAS(f1, f2);
        // narrowing insert of sorted-4 (9+7+5+3)
        float n0 = fminf(p0, f0);
        float n1 = fmaxf(p0, fminf(p1, f0));
        float n2 = fmaxf(p1, fminf(p2, f0));
        float n3 = fmaxf(p2, fminf(p3, f0));
        float n4 = fmaxf(p3, fminf(p4, f0));
        float m1 = fminf(n1, f1);
        float m2 = fmaxf(n1, fminf(n2, f1));
        float m3 = fmaxf(n2, fminf(n3, f1));
        float m4 = fmaxf(n3, fminf(n4, f1));
        float k2 = fminf(m2, f2);
        float k3 = fmaxf(m2, fminf(m3, f2));
        float k4 = fmaxf(m3, fminf(m4, f2));
        p0 = n0; p1 = m1; p2 = k2;
        p3 = fminf(k3, f3);
        p4 = fmaxf(k3, fminf(k4, f3));
    }

    if (seg != 0) {
        int o = (seg - 1) * 5;
        mbuf[lpt][o + 0] = p0;
        mbuf[lpt][o + 1] = p1;
        mbuf[lpt][o + 2] = p2;
        mbuf[lpt][o + 3] = p3;
        mbuf[lpt][o + 4] = p4;
    }
    __syncthreads();

    if (seg == 0) {
        #pragma unroll
        for (int s = 0; s < 3; s++) {
            int o = s * 5;
            merge5(p0, p1, p2, p3, p4,
                   mbuf[lpt][o + 0], mbuf[lpt][o + 1], mbuf[lpt][o + 2],
                   mbuf[lpt][o + 3], mbuf[lpt][o + 4]);
        }
        float pk[TOPK] = {p0, p1, p2, p3, p4};

        int b = p >> 14;
        float xx = x0 * x0 + x1 * x1 + x2 * x2;
        float wsum = 0.f, o0 = 0.f, o1 = 0.f, o2 = 0.f;
        #pragma unroll
        for (int k = 0; k < TOPK; k++) {
            int jk = (int)(__float_as_uint(pk[k]) & 1023u);
            float4 q = sn[jk];
            float t = fmaf(x0, q.x, fmaf(x1, q.y, fmaf(x2, q.z, q.w)));
            float dd = fmaxf(t + xx, 0.f);
            float dist = sqrtf(dd);
            float wk = -logf(fminf(dist, 1.f) - 1e-6f);
            wsum += wk;
            const float4* Tp = (const float4*)(gT + ((size_t)((b << 10) + jk)) * 12);
            float4 r0 = Tp[0], r1 = Tp[1], r2 = Tp[2];
            o0 = fmaf(wk, fmaf(r0.x, x0, fmaf(r0.y, x1, fmaf(r0.z, x2, r0.w))), o0);
            o1 = fmaf(wk, fmaf(r1.x, x0, fmaf(r1.y, x1, fmaf(r1.z, x2, r1.w))), o1);
            o2 = fmaf(wk, fmaf(r2.x, x0, fmaf(r2.y, x1, fmaf(r2.z, x2, r2.w))), o2);
        }
        float inv = 1.f / wsum;
        out[p * 3 + 0] = o0 * inv;
        out[p * 3 + 1] = o1 * inv;
        out[p * 3 + 2] = o2 * inv;
    }
}

// ---------------------------------------------------------------------------
// Inputs (metadata order): x, cond_smpl, nodes, smpl_root_orient, smpl_trans,
// scale, W1, b1, W2, b2.  Output: float32 (B, N, 3).
// ---------------------------------------------------------------------------
extern "C" void kernel_launch(void* const* d_in, const int* in_sizes, int n_in,
                              void* d_out, int out_size) {
    const float* x     = (const float*)d_in[0];
    const float* cond  = (const float*)d_in[1];
    const float* nodes = (const float*)d_in[2];
    const float* root  = (const float*)d_in[3];
    const float* trans = (const float*)d_in[4];
    const float* scale = (const float*)d_in[5];
    const float* W1    = (const float*)d_in[6];
    const float* b1    = (const float*)d_in[7];
    const float* W2    = (const float*)d_in[8];
    const float* b2    = (const float*)d_in[9];
    float* out = (float*)d_out;

    tmat_fused_kernel<<<BATCH * 128, 256>>>(cond, W1, b1, W2, nodes,
                                            root, trans, scale, b2);
    knn_kernel<<<NTOT / 64, 256>>>(x, nodes, out);
}

// round 9
// speedup vs baseline: 1.4041x; 1.2198x over previous
#include <cuda_runtime.h>
#include <cstdint>

// Problem constants (fixed by setup_inputs)
#define BATCH 4
#define NPTS  16384
#define NTOT  (BATCH * NPTS)   // 65536
#define NJ    1024
#define CCOND 69
#define HID   256
#define TOPK  5

// Scratch (device global; no dynamic allocation allowed)
__device__ float gT[BATCH * NJ * 12];     // top 3x4 rows of final transforms

// ---------------------------------------------------------------------------
// Rodrigues exactly as reference.
// ---------------------------------------------------------------------------
__device__ __forceinline__ void rodrigues_mat(float a0, float a1, float a2, float* R) {
    float e0 = a0 + 1e-8f, e1 = a1 + 1e-8f, e2 = a2 + 1e-8f;
    float angle = sqrtf(e0 * e0 + e1 * e1 + e2 * e2);
    float half = 0.5f * angle;
    float s = sinf(half), c = cosf(half);
    float inv = 1.0f / angle;
    float qw = c, qx = s * a0 * inv, qy = s * a1 * inv, qz = s * a2 * inv;
    float qn = rsqrtf(qw * qw + qx * qx + qy * qy + qz * qz);
    qw *= qn; qx *= qn; qy *= qn; qz *= qn;
    float w2 = qw * qw, x2 = qx * qx, y2 = qy * qy, z2 = qz * qz;
    float wx = qw * qx, wy = qw * qy, wz = qw * qz;
    float xy = qx * qy, xz = qx * qz, yz = qy * qz;
    R[0] = w2 + x2 - y2 - z2; R[1] = 2.f * xy - 2.f * wz; R[2] = 2.f * wy + 2.f * xz;
    R[3] = 2.f * wz + 2.f * xy; R[4] = w2 - x2 + y2 - z2; R[5] = 2.f * yz - 2.f * wx;
    R[6] = 2.f * xz - 2.f * wy; R[7] = 2.f * wx + 2.f * yz; R[8] = w2 - x2 - y2 + z2;
}

// ---------------------------------------------------------------------------
// Fused kernel AB (unchanged): one block = (b, 8 j's), 256 threads.
// ---------------------------------------------------------------------------
__global__ __launch_bounds__(256) void tmat_fused_kernel(
        const float* __restrict__ cond,
        const float* __restrict__ W1,
        const float* __restrict__ b1,
        const float* __restrict__ W2,
        const float* __restrict__ nodes,
        const float* __restrict__ root,
        const float* __restrict__ trans,
        const float* __restrict__ scale,
        const float* __restrict__ b2) {
    __shared__ float4 sP[HID];
    __shared__ float  sW2[HID * 8];
    __shared__ float  sRr[9];
    __shared__ float  sAux[4];

    int b = blockIdx.x >> 7;
    int jbase = (blockIdx.x & 127) << 3;
    int t = threadIdx.x;
    const float* cb = cond + b * CCOND;

    float s0 = 0.f, s1 = 0.f, s2 = 0.f, s3 = 0.f;
    #pragma unroll
    for (int c = 0; c < 68; c += 4) {
        s0 = fmaf(cb[c + 0], W1[(3 + c) * HID + t], s0);
        s1 = fmaf(cb[c + 1], W1[(4 + c) * HID + t], s1);
        s2 = fmaf(cb[c + 2], W1[(5 + c) * HID + t], s2);
        s3 = fmaf(cb[c + 3], W1[(6 + c) * HID + t], s3);
    }
    s0 = fmaf(cb[68], W1[71 * HID + t], s0);
    float base = b1[t] + ((s0 + s1) + (s2 + s3));
    sP[t] = make_float4(W1[t], W1[HID + t], W1[2 * HID + t], base);

    #pragma unroll
    for (int o = 0; o < 6; o++) sW2[t * 8 + o] = W2[t * 6 + o];
    sW2[t * 8 + 6] = 0.f;
    sW2[t * 8 + 7] = 0.f;

    if (t == 0) {
        float R[9];
        rodrigues_mat(root[b * 3], root[b * 3 + 1], root[b * 3 + 2], R);
        #pragma unroll
        for (int i = 0; i < 9; i++) sRr[i] = R[i];
        sAux[0] = scale[b];
        sAux[1] = trans[b * 3 + 0];
        sAux[2] = trans[b * 3 + 1];
        sAux[3] = trans[b * 3 + 2];
    }
    __syncthreads();

    int w = t >> 5;
    int lane = t & 31;
    int j = jbase + w;

    float n0 = nodes[j * 3], n1 = nodes[j * 3 + 1], n2 = nodes[j * 3 + 2];
    float a0 = 0.f, a1 = 0.f, a2 = 0.f, a3 = 0.f, a4 = 0.f, a5 = 0.f;

    #pragma unroll
    for (int i = 0; i < 8; i++) {
        int tt = lane + (i << 5);
        float4 p = sP[tt];
        float h = fmaf(n0, p.x, fmaf(n1, p.y, fmaf(n2, p.z, p.w)));
        h = fmaxf(h, 0.f);
        const float4* w2v = (const float4*)(sW2 + tt * 8);
        float4 lo = w2v[0];
        float4 hi = w2v[1];
        a0 = fmaf(h, lo.x, a0); a1 = fmaf(h, lo.y, a1); a2 = fmaf(h, lo.z, a2);
        a3 = fmaf(h, lo.w, a3); a4 = fmaf(h, hi.x, a4); a5 = fmaf(h, hi.y, a5);
    }
    #pragma unroll
    for (int off = 16; off; off >>= 1) {
        a0 += __shfl_xor_sync(0xffffffffu, a0, off);
        a1 += __shfl_xor_sync(0xffffffffu, a1, off);
        a2 += __shfl_xor_sync(0xffffffffu, a2, off);
        a3 += __shfl_xor_sync(0xffffffffu, a3, off);
        a4 += __shfl_xor_sync(0xffffffffu, a4, off);
        a5 += __shfl_xor_sync(0xffffffffu, a5, off);
    }
    if (lane == 0) {
        float r0 = a0 + b2[0], r1 = a1 + b2[1], r2 = a2 + b2[2];
        float u0 = a3 + b2[3], u1 = a4 + b2[4], u2 = a5 + b2[5];
        float R[9];
        rodrigues_mat(r0, r1, r2, R);
        float s = sAux[0];
        float M[12];
        #pragma unroll
        for (int r = 0; r < 3; r++) {
            float c0 = sRr[r * 3], c1 = sRr[r * 3 + 1], c2 = sRr[r * 3 + 2];
            M[r * 4 + 0] = s * (c0 * R[0] + c1 * R[3] + c2 * R[6]);
            M[r * 4 + 1] = s * (c0 * R[1] + c1 * R[4] + c2 * R[7]);
            M[r * 4 + 2] = s * (c0 * R[2] + c1 * R[5] + c2 * R[8]);
            M[r * 4 + 3] = s * (c0 * u0 + c1 * u1 + c2 * u2) + sAux[1 + r] * s;
        }
        float4* dst = (float4*)(gT + ((size_t)((b << 10) + j)) * 12);
        dst[0] = make_float4(M[0], M[1], M[2], M[3]);
        dst[1] = make_float4(M[4], M[5], M[6], M[7]);
        dst[2] = make_float4(M[8], M[9], M[10], M[11]);
    }
}

// Narrowing merge of a sorted-5 list (b0<=..<=b4) into sorted top-5 p0..p4.
__device__ __forceinline__ void merge5(float& p0, float& p1, float& p2,
                                       float& p3, float& p4,
                                       float b0, float b1, float b2,
                                       float b3, float b4) {
    float n0 = fminf(p0, b0);
    float n1 = fmaxf(p0, fminf(p1, b0));
    float n2 = fmaxf(p1, fminf(p2, b0));
    float n3 = fmaxf(p2, fminf(p3, b0));
    float n4 = fmaxf(p3, fminf(p4, b0));
    float m1 = fminf(n1, b1);
    float m2 = fmaxf(n1, fminf(n2, b1));
    float m3 = fmaxf(n2, fminf(n3, b1));
    float m4 = fmaxf(n3, fminf(n4, b1));
    float k2 = fminf(m2, b2);
    float k3 = fmaxf(m2, fminf(m3, b2));
    float k4 = fmaxf(m3, fminf(m4, b2));
    float l3 = fminf(k3, b3);
    float l4 = fmaxf(k3, fminf(k4, b3));
    p0 = n0; p1 = m1; p2 = k2; p3 = l3;
    p4 = fmaxf(l3, fminf(l4, b4));
}

// ---------------------------------------------------------------------------
// Kernel C: 256 threads = 64 points x 4 candidate-segments (256 js each).
// TWO-LEVEL exact selection:
//  Pass 1: per chunk of 4 candidates keep only the chunk-minimum, packed with
//    the 6-bit local chunk id (low mantissa bits, order-preserving), and
//    maintain a sorted top-6 chunk list (3 + 1 + 11 ops / 4 cands).
//    Lemma: every true top-5 node lies in a top-5-by-min chunk; keeping 6
//    adds margin against the 6-bit quantization.
//  Pass 2: rescan the 6 surviving chunks (24 cands) with exact metrics packed
//    with 10-bit global j, building the segment's sorted top-5.
//  Segments merged via smem; winners' exact distances recomputed in epilogue.
// Grid: 1024 blocks x 256 threads.
// ---------------------------------------------------------------------------
__global__ __launch_bounds__(256, 6) void knn_kernel(
        const float* __restrict__ x,
        const float* __restrict__ nodes,
        float* __restrict__ out) {
    __shared__ float4 sn[NJ];
    __shared__ float  mbuf[64][17];   // 3 foreign segs * 5, odd stride
    int tid = threadIdx.x;
    for (int e = tid; e < NJ; e += 256) {
        float v0 = nodes[e * 3], v1 = nodes[e * 3 + 1], v2 = nodes[e * 3 + 2];
        sn[e] = make_float4(-2.f * v0, -2.f * v1, -2.f * v2,
                            v0 * v0 + v1 * v1 + v2 * v2);
    }
    __syncthreads();

    int lpt = tid & 63;
    int seg = tid >> 6;                  // 0..3
    int p = blockIdx.x * 64 + lpt;       // 0..65535
    float x0 = x[p * 3], x1 = x[p * 3 + 1], x2 = x[p * 3 + 2];
    int jbase = seg << 8;                // 256 candidates per segment

    // ---- Pass 1: top-6 chunks by chunk-min ----
    float c0 = 1e30f, c1 = 1e30f, c2 = 1e30f,
          c3 = 1e30f, c4 = 1e30f, c5 = 1e30f;

    #pragma unroll 2
    for (int c = 0; c < 64; c++) {
        int j = jbase + (c << 2);
        float4 q0 = sn[j], q1 = sn[j + 1], q2 = sn[j + 2], q3 = sn[j + 3];
        float t0 = fmaf(x0, q0.x, fmaf(x1, q0.y, fmaf(x2, q0.z, q0.w)));
        float t1 = fmaf(x0, q1.x, fmaf(x1, q1.y, fmaf(x2, q1.z, q1.w)));
        float t2 = fmaf(x0, q2.x, fmaf(x1, q2.y, fmaf(x2, q2.z, q2.w)));
        float t3 = fmaf(x0, q3.x, fmaf(x1, q3.y, fmaf(x2, q3.z, q3.w)));
        float m = fminf(fminf(t0, t1), fminf(t2, t3));
        float f = __uint_as_float((__float_as_uint(m) & 0xFFFFFFC0u) | (unsigned)c);
        // insert into sorted-6 (11 FMNMX, unconditional narrowing chain)
        float n0 = fminf(c0, f);
        float n1 = fmaxf(c0, fminf(c1, f));
        float n2 = fmaxf(c1, fminf(c2, f));
        float n3 = fmaxf(c2, fminf(c3, f));
        float n4 = fmaxf(c3, fminf(c4, f));
        float n5 = fmaxf(c4, fminf(c5, f));
        c0 = n0; c1 = n1; c2 = n2; c3 = n3; c4 = n4; c5 = n5;
    }

    // ---- Pass 2: exact rescan of the 6 surviving chunks ----
    float p0 = 1e30f, p1 = 1e30f, p2 = 1e30f, p3 = 1e30f, p4 = 1e30f;
    float cl[6] = {c0, c1, c2, c3, c4, c5};
    #pragma unroll
    for (int s = 0; s < 6; s++) {
        int lc = (int)(__float_as_uint(cl[s]) & 63u);
        int j = jbase + (lc << 2);
        #pragma unroll
        for (int u = 0; u < 4; u++) {
            float4 q = sn[j + u];
            float t = fmaf(x0, q.x, fmaf(x1, q.y, fmaf(x2, q.z, q.w)));
            float f = __uint_as_float((__float_as_uint(t) & 0xFFFFFC00u) |
                                      (unsigned)(j + u));
            float n0 = fminf(p0, f);
            float n1 = fmaxf(p0, fminf(p1, f));
            float n2 = fmaxf(p1, fminf(p2, f));
            float n3 = fmaxf(p2, fminf(p3, f));
            float n4 = fmaxf(p3, fminf(p4, f));
            p0 = n0; p1 = n1; p2 = n2; p3 = n3; p4 = n4;
        }
    }

    if (seg != 0) {
        int o = (seg - 1) * 5;
        mbuf[lpt][o + 0] = p0;
        mbuf[lpt][o + 1] = p1;
        mbuf[lpt][o + 2] = p2;
        mbuf[lpt][o + 3] = p3;
        mbuf[lpt][o + 4] = p4;
    }
    __syncthreads();

    if (seg == 0) {
        #pragma unroll
        for (int s = 0; s < 3; s++) {
            int o = s * 5;
            merge5(p0, p1, p2, p3, p4,
                   mbuf[lpt][o + 0], mbuf[lpt][o + 1], mbuf[lpt][o + 2],
                   mbuf[lpt][o + 3], mbuf[lpt][o + 4]);
        }
        float pk[TOPK] = {p0, p1, p2, p3, p4};

        int b = p >> 14;
        float xx = x0 * x0 + x1 * x1 + x2 * x2;
        float wsum = 0.f, o0 = 0.f, o1 = 0.f, o2 = 0.f;
        #pragma unroll
        for (int k = 0; k < TOPK; k++) {
            int jk = (int)(__float_as_uint(pk[k]) & 1023u);
            float4 q = sn[jk];
            float t = fmaf(x0, q.x, fmaf(x1, q.y, fmaf(x2, q.z, q.w)));
            float dd = fmaxf(t + xx, 0.f);
            float dist = sqrtf(dd);
            float wk = -logf(fminf(dist, 1.f) - 1e-6f);
            wsum += wk;
            const float4* Tp = (const float4*)(gT + ((size_t)((b << 10) + jk)) * 12);
            float4 r0 = Tp[0], r1 = Tp[1], r2 = Tp[2];
            o0 = fmaf(wk, fmaf(r0.x, x0, fmaf(r0.y, x1, fmaf(r0.z, x2, r0.w))), o0);
            o1 = fmaf(wk, fmaf(r1.x, x0, fmaf(r1.y, x1, fmaf(r1.z, x2, r1.w))), o1);
            o2 = fmaf(wk, fmaf(r2.x, x0, fmaf(r2.y, x1, fmaf(r2.z, x2, r2.w))), o2);
        }
        float inv = 1.f / wsum;
        out[p * 3 + 0] = o0 * inv;
        out[p * 3 + 1] = o1 * inv;
        out[p * 3 + 2] = o2 * inv;
    }
}

// ---------------------------------------------------------------------------
// Inputs (metadata order): x, cond_smpl, nodes, smpl_root_orient, smpl_trans,
// scale, W1, b1, W2, b2.  Output: float32 (B, N, 3).
// ---------------------------------------------------------------------------
extern "C" void kernel_launch(void* const* d_in, const int* in_sizes, int n_in,
                              void* d_out, int out_size) {
    const float* x     = (const float*)d_in[0];
    const float* cond  = (const float*)d_in[1];
    const float* nodes = (const float*)d_in[2];
    const float* root  = (const float*)d_in[3];
    const float* trans = (const float*)d_in[4];
    const float* scale = (const float*)d_in[5];
    const float* W1    = (const float*)d_in[6];
    const float* b1    = (const float*)d_in[7];
    const float* W2    = (const float*)d_in[8];
    const float* b2    = (const float*)d_in[9];
    float* out = (float*)d_out;

    tmat_fused_kernel<<<BATCH * 128, 256>>>(cond, W1, b1, W2, nodes,
                                            root, trans, scale, b2);
    knn_kernel<<<NTOT / 64, 256>>>(x, nodes, out);
}